// round 1
// baseline (speedup 1.0000x reference)
#include <cuda_runtime.h>
#include <cuda_bf16.h>
#include <cstdint>
#include <cfloat>

// Problem constants
#define Bz 32
#define Sz 2048
#define Dz 1024
#define Ez 16
#define Kz 4
#define Oz 1024
#define KDz (Kz * Dz)   // 4096

// ---------------------------------------------------------------------------
// Scratch (device globals; no allocations allowed)
// ---------------------------------------------------------------------------
__device__ float g_logits[(size_t)Bz * Sz * Ez];        // [b][s][e]   4 MB
__device__ float g_topv[Bz * Ez * Kz];                  // gate probs
__device__ int   g_topi[Bz * Ez * Kz];                  // token indices
__device__ float g_inp[(size_t)Ez * Bz * KDz];          // [e][b][i]   8 MB
__device__ float g_h1[(size_t)Ez * Bz * Oz];            // [e][b][o]   2 MB
__device__ float g_h2[(size_t)Ez * Bz * Oz];            // [e][b][o]   2 MB

// ---------------------------------------------------------------------------
// Kernel 1: gating logits[b][s][e] = x[b,s,:] . Wg[:,e] + bg[e]
// block = one (b,s) token, 128 threads. Each thread accumulates all 16
// experts over d = tid + j*128. Wg row (16 floats) read as 4x float4.
// ---------------------------------------------------------------------------
__global__ void __launch_bounds__(128) gate_kernel(
    const float* __restrict__ x, const float* __restrict__ Wg,
    const float* __restrict__ bg, float* __restrict__ logits)
{
    const int s = blockIdx.x;
    const int b = blockIdx.y;
    const int tid = threadIdx.x;
    const float* xr = x + ((size_t)b * Sz + s) * Dz;

    float acc[16];
#pragma unroll
    for (int e = 0; e < 16; e++) acc[e] = 0.f;

#pragma unroll
    for (int j = 0; j < 8; j++) {
        const int d = tid + j * 128;
        const float xv = __ldg(xr + d);
        const float4* wr = reinterpret_cast<const float4*>(Wg + (size_t)d * Ez);
#pragma unroll
        for (int q = 0; q < 4; q++) {
            float4 w = __ldg(wr + q);
            acc[q * 4 + 0] = fmaf(xv, w.x, acc[q * 4 + 0]);
            acc[q * 4 + 1] = fmaf(xv, w.y, acc[q * 4 + 1]);
            acc[q * 4 + 2] = fmaf(xv, w.z, acc[q * 4 + 2]);
            acc[q * 4 + 3] = fmaf(xv, w.w, acc[q * 4 + 3]);
        }
    }

    // two-stage shared reduction: part[128][16] (pad 17 -> conflict-free)
    __shared__ float part[128][17];
    __shared__ float p2[8][16];
#pragma unroll
    for (int e = 0; e < 16; e++) part[tid][e] = acc[e];
    __syncthreads();

    // stage A: 128 threads -> (e = tid&15, g = tid>>4), each sums 16 rows
    {
        const int e = tid & 15;
        const int g = tid >> 4;
        float s0 = 0.f;
#pragma unroll
        for (int r = 0; r < 16; r++) s0 += part[g * 16 + r][e];
        p2[g][e] = s0;
    }
    __syncthreads();

    // stage B: 16 threads finalize
    if (tid < 16) {
        float s0 = 0.f;
#pragma unroll
        for (int g = 0; g < 8; g++) s0 += p2[g][tid];
        logits[((size_t)b * Sz + s) * Ez + tid] = s0 + bg[tid];
    }
}

// ---------------------------------------------------------------------------
// Kernel 2: per (b,e): softmax-over-S stats + top-4.
// softmax over S is monotone in logits -> top-4 of probs == top-4 of logits.
// gate value = exp(logit - max) / sum_s exp(logit - max).
// ---------------------------------------------------------------------------
__global__ void __launch_bounds__(128) topk_kernel(
    const float* __restrict__ logits,
    float* __restrict__ topv, int* __restrict__ topi)
{
    const int e = blockIdx.x;
    const int b = blockIdx.y;
    const int tid = threadIdx.x;
    const float* L = logits + (size_t)b * Sz * Ez + e;  // stride Ez

    __shared__ float redf[4];
    __shared__ float s_gmax, s_gsum;
    __shared__ int   chosen[4];
    __shared__ float rv[4];
    __shared__ int   ri[4];

    // ---- max over S ----
    float m = -FLT_MAX;
    for (int s = tid; s < Sz; s += 128) m = fmaxf(m, L[(size_t)s * Ez]);
#pragma unroll
    for (int off = 16; off; off >>= 1) m = fmaxf(m, __shfl_xor_sync(0xffffffffu, m, off));
    if ((tid & 31) == 0) redf[tid >> 5] = m;
    __syncthreads();
    if (tid == 0) s_gmax = fmaxf(fmaxf(redf[0], redf[1]), fmaxf(redf[2], redf[3]));
    __syncthreads();
    const float gmax = s_gmax;

    // ---- sum exp ----
    float sum = 0.f;
    for (int s = tid; s < Sz; s += 128) sum += expf(L[(size_t)s * Ez] - gmax);
#pragma unroll
    for (int off = 16; off; off >>= 1) sum += __shfl_xor_sync(0xffffffffu, sum, off);
    __syncthreads();
    if ((tid & 31) == 0) redf[tid >> 5] = sum;
    __syncthreads();
    if (tid == 0) s_gsum = redf[0] + redf[1] + redf[2] + redf[3];
    __syncthreads();
    const float gsum = s_gsum;

    // ---- 4 sequential argmax passes (descending order, ties -> lower idx) ----
    for (int kk = 0; kk < 4; kk++) {
        float bv = -FLT_MAX;
        int   bi = 0x7fffffff;
        for (int s = tid; s < Sz; s += 128) {
            bool skip = false;
            for (int j = 0; j < kk; j++) skip |= (chosen[j] == s);
            if (skip) continue;
            const float v = L[(size_t)s * Ez];
            if (v > bv || (v == bv && s < bi)) { bv = v; bi = s; }
        }
#pragma unroll
        for (int off = 16; off; off >>= 1) {
            float ov = __shfl_xor_sync(0xffffffffu, bv, off);
            int   oi = __shfl_xor_sync(0xffffffffu, bi, off);
            if (ov > bv || (ov == bv && oi < bi)) { bv = ov; bi = oi; }
        }
        if ((tid & 31) == 0) { rv[tid >> 5] = bv; ri[tid >> 5] = bi; }
        __syncthreads();
        if (tid == 0) {
            float cv = rv[0]; int ci = ri[0];
#pragma unroll
            for (int w = 1; w < 4; w++) {
                if (rv[w] > cv || (rv[w] == cv && ri[w] < ci)) { cv = rv[w]; ci = ri[w]; }
            }
            chosen[kk] = ci;
            const int base = (b * Ez + e) * Kz + kk;
            topi[base] = ci;
            topv[base] = expf(cv - gmax) / gsum;
        }
        __syncthreads();
    }
}

// ---------------------------------------------------------------------------
// Kernel 3: gather selected tokens, scale by gate prob.
// g_inp[e][b][k*D + d] = x[b, idx(b,e,k), d] * val(b,e,k)
// ---------------------------------------------------------------------------
__global__ void __launch_bounds__(256) gather_kernel(
    const float* __restrict__ x, const int* __restrict__ topi,
    const float* __restrict__ topv, float* __restrict__ inp)
{
    const int k = blockIdx.x;
    const int e = blockIdx.y;
    const int b = blockIdx.z;
    const int base = (b * Ez + e) * Kz + k;
    const int idx = topi[base];
    const float val = topv[base];
    const float4* src = reinterpret_cast<const float4*>(x + ((size_t)b * Sz + idx) * Dz);
    float4* dst = reinterpret_cast<float4*>(inp + ((size_t)e * Bz + b) * KDz + (size_t)k * Dz);
    const int t = threadIdx.x;            // 256 threads, D/4 = 256 float4
    float4 v = src[t];
    v.x *= val; v.y *= val; v.z *= val; v.w *= val;
    dst[t] = v;
}

// ---------------------------------------------------------------------------
// Kernel 4: grouped GEMM layer.
// in : [E][B][NI], W : [E][NI][O], bias : [E][O]
// out: FINAL ? out[b][e][o] : [E][B][O]
// block = (o-tile of 128, expert e); each thread: 1 o col, 32 batch accs.
// Per k-chunk of 32: 32 coalesced W loads (reused 32x each), input tile in
// SMEM (pad 36 -> aligned LDS.128, bounded conflicts).
// ---------------------------------------------------------------------------
template <int NI, bool RELU, bool FINAL>
__global__ void __launch_bounds__(128) mlp_kernel(
    const float* __restrict__ in, const float* __restrict__ W,
    const float* __restrict__ bias, float* __restrict__ out)
{
    const int e = blockIdx.y;
    const int o = blockIdx.x * 128 + threadIdx.x;
    const float* inE = in + (size_t)e * Bz * NI;
    const float* We = W + (size_t)e * NI * Oz + o;

    float acc[32];
#pragma unroll
    for (int b = 0; b < 32; b++) acc[b] = 0.f;

    __shared__ float s_in[32][36];  // [ii][b], pad 36 for aligned float4 rows

    for (int i0 = 0; i0 < NI; i0 += 32) {
        __syncthreads();
#pragma unroll
        for (int t = threadIdx.x; t < 1024; t += 128) {
            const int bb = t >> 5;
            const int ii = t & 31;
            s_in[ii][bb] = inE[(size_t)bb * NI + i0 + ii];
        }
        __syncthreads();

        float w[32];
#pragma unroll
        for (int ii = 0; ii < 32; ii++) w[ii] = __ldg(We + (size_t)(i0 + ii) * Oz);

#pragma unroll
        for (int ii = 0; ii < 32; ii++) {
            const float4* row = reinterpret_cast<const float4*>(&s_in[ii][0]);
#pragma unroll
            for (int bq = 0; bq < 8; bq++) {
                const float4 v = row[bq];
                acc[bq * 4 + 0] = fmaf(v.x, w[ii], acc[bq * 4 + 0]);
                acc[bq * 4 + 1] = fmaf(v.y, w[ii], acc[bq * 4 + 1]);
                acc[bq * 4 + 2] = fmaf(v.z, w[ii], acc[bq * 4 + 2]);
                acc[bq * 4 + 3] = fmaf(v.w, w[ii], acc[bq * 4 + 3]);
            }
        }
    }

    const float bs = bias[e * Oz + o];
#pragma unroll
    for (int b = 0; b < 32; b++) {
        float v = acc[b] + bs;
        if (RELU) v = fmaxf(v, 0.f);
        if (FINAL) out[((size_t)b * Ez + e) * Oz + o] = v;
        else       out[((size_t)e * Bz + b) * Oz + o] = v;
    }
}

// ---------------------------------------------------------------------------
// Launch
// ---------------------------------------------------------------------------
extern "C" void kernel_launch(void* const* d_in, const int* in_sizes, int n_in,
                              void* d_out, int out_size)
{
    const float* x  = (const float*)d_in[0];
    const float* Wg = (const float*)d_in[1];
    const float* bg = (const float*)d_in[2];
    const float* W1 = (const float*)d_in[3];
    const float* b1 = (const float*)d_in[4];
    const float* W2 = (const float*)d_in[5];
    const float* b2 = (const float*)d_in[6];
    const float* W3 = (const float*)d_in[7];
    const float* b3 = (const float*)d_in[8];
    float* out = (float*)d_out;

    float* logits; cudaGetSymbolAddress((void**)&logits, g_logits);
    float* topv;   cudaGetSymbolAddress((void**)&topv, g_topv);
    int*   topi;   cudaGetSymbolAddress((void**)&topi, g_topi);
    float* inp;    cudaGetSymbolAddress((void**)&inp, g_inp);
    float* h1;     cudaGetSymbolAddress((void**)&h1, g_h1);
    float* h2;     cudaGetSymbolAddress((void**)&h2, g_h2);

    gate_kernel<<<dim3(Sz, Bz), 128>>>(x, Wg, bg, logits);
    topk_kernel<<<dim3(Ez, Bz), 128>>>(logits, topv, topi);
    gather_kernel<<<dim3(Kz, Ez, Bz), 256>>>(x, topi, topv, inp);
    mlp_kernel<KDz, true,  false><<<dim3(Oz / 128, Ez), 128>>>(inp, W1, b1, h1);
    mlp_kernel<Oz,  true,  false><<<dim3(Oz / 128, Ez), 128>>>(h1, W2, b2, h2);
    mlp_kernel<Oz,  false, true ><<<dim3(Oz / 128, Ez), 128>>>(h2, W3, b3, out);
}

// round 2
// speedup vs baseline: 3.0792x; 3.0792x over previous
#include <cuda_runtime.h>
#include <cuda_bf16.h>
#include <cstdint>
#include <cfloat>

#define Bz 32
#define Sz 2048
#define Dz 1024
#define Ez 16
#define Kz 4
#define Oz 1024
#define KDz (Kz * Dz)   // 4096

// ---------------------------------------------------------------------------
// Scratch (device globals; no allocations allowed)
// ---------------------------------------------------------------------------
__device__ float g_logits[(size_t)Bz * Ez * Sz];        // [b][e][s]   4 MB
__device__ float g_topv[Bz * Ez * Kz];
__device__ int   g_topi[Bz * Ez * Kz];
__device__ float g_inp[(size_t)Ez * Bz * KDz];          // [e][b][i]   8 MB
__device__ float g_h1[(size_t)Ez * Bz * Oz];            // [e][b][o]   2 MB
__device__ float g_h2[(size_t)Ez * Bz * Oz];            // [e][b][o]   2 MB
__device__ float g_part[(size_t)8 * Ez * Bz * Oz];      // k-split partials 16 MB

// ---------------------------------------------------------------------------
// Kernel 1: gating. logits[b][e][s] = x[b,s,:].Wg[:,e]   (bg dropped: softmax
// over the token axis is invariant to a per-expert constant shift, and so are
// its top-k indices/values.)
// Block = 128 tokens. Wg (64KB) staged in smem ONCE per block; x tile staged
// per 32-k chunk. Thread owns 1 token x 16 expert accumulators -> no
// cross-thread reduction.
// ---------------------------------------------------------------------------
__global__ void __launch_bounds__(128) gate_kernel(
    const float* __restrict__ x, const float* __restrict__ Wg,
    float* __restrict__ logits)
{
    extern __shared__ float sm[];
    float* s_wg = sm;                 // [1024][16]
    float* s_x  = sm + Dz * Ez;       // [128][36]

    const int tid = threadIdx.x;
    const int t0  = blockIdx.x * 128;       // global token base
    const int b   = t0 >> 11;               // t0 / 2048 (blocks never straddle b)
    const int sbase = t0 & 2047;

    // stage Wg: 16384 floats = 4096 float4, 32 per thread, coalesced
    {
        const float4* wg4 = reinterpret_cast<const float4*>(Wg);
        float4* swg4 = reinterpret_cast<float4*>(s_wg);
#pragma unroll
        for (int q = 0; q < 32; q++) swg4[tid + 128 * q] = __ldg(wg4 + tid + 128 * q);
    }

    float acc[16];
#pragma unroll
    for (int e = 0; e < 16; e++) acc[e] = 0.f;

    const float* xb = x + (size_t)t0 * Dz;

    for (int k0 = 0; k0 < Dz; k0 += 32) {
        __syncthreads();   // protect s_x from previous iteration's readers
        // stage x tile: 128 tokens x 32 k = 1024 float4-chunks? -> 4096 floats
#pragma unroll
        for (int q = 0; q < 8; q++) {
            const int idx = tid + 128 * q;      // 0..1023 float4 slots
            const int tt  = idx >> 3;           // token 0..127
            const int c   = idx & 7;            // float4 col 0..7
            float4 v = __ldg(reinterpret_cast<const float4*>(xb + (size_t)tt * Dz + k0) + c);
            *reinterpret_cast<float4*>(&s_x[tt * 36 + 4 * c]) = v;
        }
        __syncthreads();

#pragma unroll
        for (int kq = 0; kq < 8; kq++) {
            const float4 xv = *reinterpret_cast<const float4*>(&s_x[tid * 36 + kq * 4]);
#pragma unroll
            for (int j = 0; j < 4; j++) {
                const float xs = (&xv.x)[j];
                const float4* wr = reinterpret_cast<const float4*>(&s_wg[(size_t)(k0 + kq * 4 + j) * Ez]);
                const float4 w0 = wr[0], w1 = wr[1], w2 = wr[2], w3 = wr[3];
                acc[0]  = fmaf(xs, w0.x, acc[0]);  acc[1]  = fmaf(xs, w0.y, acc[1]);
                acc[2]  = fmaf(xs, w0.z, acc[2]);  acc[3]  = fmaf(xs, w0.w, acc[3]);
                acc[4]  = fmaf(xs, w1.x, acc[4]);  acc[5]  = fmaf(xs, w1.y, acc[5]);
                acc[6]  = fmaf(xs, w1.z, acc[6]);  acc[7]  = fmaf(xs, w1.w, acc[7]);
                acc[8]  = fmaf(xs, w2.x, acc[8]);  acc[9]  = fmaf(xs, w2.y, acc[9]);
                acc[10] = fmaf(xs, w2.z, acc[10]); acc[11] = fmaf(xs, w2.w, acc[11]);
                acc[12] = fmaf(xs, w3.x, acc[12]); acc[13] = fmaf(xs, w3.y, acc[13]);
                acc[14] = fmaf(xs, w3.z, acc[14]); acc[15] = fmaf(xs, w3.w, acc[15]);
            }
        }
    }

    // write logits[b][e][sbase+tid]; per-e warp-coalesced
#pragma unroll
    for (int e = 0; e < 16; e++)
        logits[((size_t)b * Ez + e) * Sz + sbase + tid] = acc[e];
}

// ---------------------------------------------------------------------------
// Kernel 2: per (b,e) softmax stats + top-4 from an smem-resident row.
// top-4 of softmax == top-4 of logits (monotone). Ties -> lower index.
// ---------------------------------------------------------------------------
__global__ void __launch_bounds__(256) topk_kernel(
    const float* __restrict__ logits,
    float* __restrict__ topv, int* __restrict__ topi)
{
    const int e = blockIdx.x;
    const int b = blockIdx.y;
    const int tid = threadIdx.x;
    const int wid = tid >> 5;
    const float* L = logits + ((size_t)b * Ez + e) * Sz;

    __shared__ float sl[Sz];
    __shared__ float redf[8];
    __shared__ int   redi[8];
    __shared__ float s_gmax, s_gsum;

    // load + running max
    float m = -FLT_MAX;
#pragma unroll
    for (int q = 0; q < 8; q++) {
        const int s = tid + q * 256;
        const float v = __ldg(L + s);
        sl[s] = v;
        m = fmaxf(m, v);
    }
#pragma unroll
    for (int off = 16; off; off >>= 1) m = fmaxf(m, __shfl_xor_sync(0xffffffffu, m, off));
    if ((tid & 31) == 0) redf[wid] = m;
    __syncthreads();
    if (tid == 0) {
        float g = redf[0];
#pragma unroll
        for (int w = 1; w < 8; w++) g = fmaxf(g, redf[w]);
        s_gmax = g;
    }
    __syncthreads();
    const float gmax = s_gmax;

    // sum of exp
    float sum = 0.f;
#pragma unroll
    for (int q = 0; q < 8; q++) sum += expf(sl[tid + q * 256] - gmax);
#pragma unroll
    for (int off = 16; off; off >>= 1) sum += __shfl_xor_sync(0xffffffffu, sum, off);
    __syncthreads();
    if ((tid & 31) == 0) redf[wid] = sum;
    __syncthreads();
    if (tid == 0) {
        float g = 0.f;
#pragma unroll
        for (int w = 0; w < 8; w++) g += redf[w];
        s_gsum = g;
    }
    __syncthreads();
    const float gsum = s_gsum;

    // 4 sequential argmax passes; selected entries knocked out to -inf
    for (int kk = 0; kk < 4; kk++) {
        float bv = -FLT_MAX;
        int   bi = 0x7fffffff;
#pragma unroll
        for (int q = 0; q < 8; q++) {
            const int s = tid + q * 256;
            const float v = sl[s];
            if (v > bv || (v == bv && s < bi)) { bv = v; bi = s; }
        }
#pragma unroll
        for (int off = 16; off; off >>= 1) {
            const float ov = __shfl_xor_sync(0xffffffffu, bv, off);
            const int   oi = __shfl_xor_sync(0xffffffffu, bi, off);
            if (ov > bv || (ov == bv && oi < bi)) { bv = ov; bi = oi; }
        }
        if ((tid & 31) == 0) { redf[wid] = bv; redi[wid] = bi; }
        __syncthreads();
        if (tid == 0) {
            float cv = redf[0]; int ci = redi[0];
#pragma unroll
            for (int w = 1; w < 8; w++) {
                if (redf[w] > cv || (redf[w] == cv && redi[w] < ci)) { cv = redf[w]; ci = redi[w]; }
            }
            const int base = (b * Ez + e) * Kz + kk;
            topi[base] = ci;
            topv[base] = expf(cv - gmax) / gsum;
            sl[ci] = -FLT_MAX;   // knock out for next pass
        }
        __syncthreads();
    }
}

// ---------------------------------------------------------------------------
// Kernel 3: gather selected tokens, scale by gate prob.
// ---------------------------------------------------------------------------
__global__ void __launch_bounds__(256) gather_kernel(
    const float* __restrict__ x, const int* __restrict__ topi,
    const float* __restrict__ topv, float* __restrict__ inp)
{
    const int k = blockIdx.x;
    const int e = blockIdx.y;
    const int b = blockIdx.z;
    const int base = (b * Ez + e) * Kz + k;
    const int idx = topi[base];
    const float val = topv[base];
    const float4* src = reinterpret_cast<const float4*>(x + ((size_t)b * Sz + idx) * Dz);
    float4* dst = reinterpret_cast<float4*>(inp + ((size_t)e * Bz + b) * KDz + (size_t)k * Dz);
    const int t = threadIdx.x;
    float4 v = src[t];
    v.x *= val; v.y *= val; v.z *= val; v.w *= val;
    dst[t] = v;
}

// ---------------------------------------------------------------------------
// Kernel 4: split-K partial GEMM.
// in : [E][B][NI], W : [E][NI][O]
// part[slice][e][b][o] = sum over k in slice
// block = (o-tile 128, e, slice of 512 k), 256 threads:
//   o = bx*128 + (tid&127), batch-half bh = tid>>7 -> acc[16].
// ---------------------------------------------------------------------------
template <int NI>
__global__ void __launch_bounds__(256) mlp_partial_kernel(
    const float* __restrict__ in, const float* __restrict__ W,
    float* __restrict__ part)
{
    const int tid = threadIdx.x;
    const int e = blockIdx.y;
    const int slice = blockIdx.z;
    const int o = blockIdx.x * 128 + (tid & 127);
    const int bh = tid >> 7;                       // 0/1 -> batches bh*16..+15

    const float* inE = in + (size_t)e * Bz * NI;
    const float* We  = W + (size_t)e * NI * Oz + o;

    float acc[16];
#pragma unroll
    for (int r = 0; r < 16; r++) acc[r] = 0.f;

    __shared__ float s_in[32][36];   // [k within chunk][batch], 16B-aligned rows

    const int kbeg = slice * 512;
    for (int i0 = kbeg; i0 < kbeg + 512; i0 += 32) {
        __syncthreads();
#pragma unroll
        for (int q = 0; q < 4; q++) {
            const int idx = tid + q * 256;   // 0..1023
            const int bb = idx >> 5;         // batch 0..31
            const int ii = idx & 31;         // k 0..31
            s_in[ii][bb] = inE[(size_t)bb * NI + i0 + ii];
        }
        __syncthreads();

        float w[32];
#pragma unroll
        for (int ii = 0; ii < 32; ii++) w[ii] = __ldg(We + (size_t)(i0 + ii) * Oz);

#pragma unroll
        for (int ii = 0; ii < 32; ii++) {
            const float4* row = reinterpret_cast<const float4*>(&s_in[ii][bh * 16]);
#pragma unroll
            for (int bq = 0; bq < 4; bq++) {
                const float4 v = row[bq];
                acc[bq * 4 + 0] = fmaf(v.x, w[ii], acc[bq * 4 + 0]);
                acc[bq * 4 + 1] = fmaf(v.y, w[ii], acc[bq * 4 + 1]);
                acc[bq * 4 + 2] = fmaf(v.z, w[ii], acc[bq * 4 + 2]);
                acc[bq * 4 + 3] = fmaf(v.w, w[ii], acc[bq * 4 + 3]);
            }
        }
    }

    float* dst = part + (((size_t)slice * Ez + e) * Bz + bh * 16) * Oz + o;
#pragma unroll
    for (int r = 0; r < 16; r++) dst[(size_t)r * Oz] = acc[r];
}

// ---------------------------------------------------------------------------
// Kernel 5: combine slices + bias (+ReLU) -> [e][b][o] or final [b][e][o].
// One float4 per thread; grid 512 x 256.
// ---------------------------------------------------------------------------
template <int NS, bool RELU, bool FINAL>
__global__ void __launch_bounds__(256) combine_kernel(
    const float* __restrict__ part, const float* __restrict__ bias,
    float* __restrict__ out)
{
    const int idx = blockIdx.x * 256 + threadIdx.x;   // float4 index
    const int o4 = idx & 255;
    const int b  = (idx >> 8) & 31;
    const int e  = idx >> 13;

    const float4* p4 = reinterpret_cast<const float4*>(part);
    const size_t base = ((size_t)e * Bz + b) * 256 + o4;

    float4 a = {0.f, 0.f, 0.f, 0.f};
#pragma unroll
    for (int sl = 0; sl < NS; sl++) {
        const float4 v = p4[(size_t)sl * (Ez * Bz * 256) + base];
        a.x += v.x; a.y += v.y; a.z += v.z; a.w += v.w;
    }
    const float4 bv = reinterpret_cast<const float4*>(bias)[e * 256 + o4];
    a.x += bv.x; a.y += bv.y; a.z += bv.z; a.w += bv.w;
    if (RELU) {
        a.x = fmaxf(a.x, 0.f); a.y = fmaxf(a.y, 0.f);
        a.z = fmaxf(a.z, 0.f); a.w = fmaxf(a.w, 0.f);
    }
    if (FINAL) reinterpret_cast<float4*>(out)[((size_t)b * Ez + e) * 256 + o4] = a;
    else       reinterpret_cast<float4*>(out)[base] = a;
}

// ---------------------------------------------------------------------------
// Launch
// ---------------------------------------------------------------------------
extern "C" void kernel_launch(void* const* d_in, const int* in_sizes, int n_in,
                              void* d_out, int out_size)
{
    const float* x  = (const float*)d_in[0];
    const float* Wg = (const float*)d_in[1];
    // d_in[2] = bg : mathematically irrelevant (softmax over tokens)
    const float* W1 = (const float*)d_in[3];
    const float* b1 = (const float*)d_in[4];
    const float* W2 = (const float*)d_in[5];
    const float* b2 = (const float*)d_in[6];
    const float* W3 = (const float*)d_in[7];
    const float* b3 = (const float*)d_in[8];
    float* out = (float*)d_out;

    float* logits; cudaGetSymbolAddress((void**)&logits, g_logits);
    float* topv;   cudaGetSymbolAddress((void**)&topv, g_topv);
    int*   topi;   cudaGetSymbolAddress((void**)&topi, g_topi);
    float* inp;    cudaGetSymbolAddress((void**)&inp, g_inp);
    float* h1;     cudaGetSymbolAddress((void**)&h1, g_h1);
    float* h2;     cudaGetSymbolAddress((void**)&h2, g_h2);
    float* part;   cudaGetSymbolAddress((void**)&part, g_part);

    const int gate_smem = (Dz * Ez + 128 * 36) * (int)sizeof(float);   // ~84 KB
    cudaFuncSetAttribute(gate_kernel, cudaFuncAttributeMaxDynamicSharedMemorySize, gate_smem);

    gate_kernel<<<(Bz * Sz) / 128, 128, gate_smem>>>(x, Wg, logits);
    topk_kernel<<<dim3(Ez, Bz), 256>>>(logits, topv, topi);
    gather_kernel<<<dim3(Kz, Ez, Bz), 256>>>(x, topi, topv, inp);

    // Layer 1: K=4096, 8 slices of 512
    mlp_partial_kernel<KDz><<<dim3(Oz / 128, Ez, 8), 256>>>(inp, W1, part);
    combine_kernel<8, true, false><<<512, 256>>>(part, b1, h1);
    // Layer 2: K=1024, 2 slices of 512
    mlp_partial_kernel<Oz><<<dim3(Oz / 128, Ez, 2), 256>>>(h1, W2, part);
    combine_kernel<2, true, false><<<512, 256>>>(part, b2, h2);
    // Layer 3
    mlp_partial_kernel<Oz><<<dim3(Oz / 128, Ez, 2), 256>>>(h2, W3, part);
    combine_kernel<2, false, true><<<512, 256>>>(part, b3, out);
}

// round 6
// speedup vs baseline: 5.5656x; 1.8075x over previous
#include <cuda_runtime.h>
#include <cuda_bf16.h>
#include <cstdint>
#include <cfloat>

#define Bz 32
#define Sz 2048
#define Dz 1024
#define Ez 16
#define Kz 4
#define Oz 1024
#define KDz (Kz * Dz)   // 4096

// ---------------------------------------------------------------------------
// Scratch (device globals; no allocations allowed)
// ---------------------------------------------------------------------------
__device__ float g_logits[(size_t)Bz * Ez * Sz];          // [b][e][s]
__device__ float g_topv[Bz * Ez * Kz];
__device__ int   g_topi[Bz * Ez * Kz];
__device__ float g_inp[(size_t)Ez * Bz * KDz];            // [e][32][4096]
__device__ float g_h1[(size_t)Ez * Bz * Oz];              // [e][32][1024]
__device__ float g_h2[(size_t)Ez * Bz * Oz];

// ---------------------------------------------------------------------------
// Helpers
// ---------------------------------------------------------------------------
__device__ __forceinline__ uint32_t smem_u32(const void* p) {
    uint32_t a;
    asm("{ .reg .u64 t; cvta.to.shared.u64 t, %1; cvt.u32.u64 %0, t; }" : "=r"(a) : "l"(p));
    return a;
}
__device__ __forceinline__ void cp_async16(uint32_t smem, const void* g) {
    asm volatile("cp.async.cg.shared.global [%0], [%1], 16;\n" :: "r"(smem), "l"(g) : "memory");
}
__device__ __forceinline__ void cp_commit() { asm volatile("cp.async.commit_group;\n" ::: "memory"); }
template <int N>
__device__ __forceinline__ void cp_wait() { asm volatile("cp.async.wait_group %0;\n" :: "n"(N) : "memory"); }

__device__ __forceinline__ uint32_t f2tf32(float f) {
    uint32_t r;
    asm("cvt.rna.tf32.f32 %0, %1;" : "=r"(r) : "f"(f));
    return r;
}
__device__ __forceinline__ void mma_tf32(float* c, const uint32_t* a, const uint32_t* b) {
    asm volatile(
        "mma.sync.aligned.m16n8k8.row.col.f32.tf32.tf32.f32 "
        "{%0,%1,%2,%3}, {%4,%5,%6,%7}, {%8,%9}, {%0,%1,%2,%3};"
        : "+f"(c[0]), "+f"(c[1]), "+f"(c[2]), "+f"(c[3])
        : "r"(a[0]), "r"(a[1]), "r"(a[2]), "r"(a[3]), "r"(b[0]), "r"(b[1]));
}

// ---------------------------------------------------------------------------
// Kernel 1: gating (fp32 scalar, exact). Unchanged from R2 (passing version).
// ---------------------------------------------------------------------------
__global__ void __launch_bounds__(128) gate_kernel(
    const float* __restrict__ x, const float* __restrict__ Wg,
    float* __restrict__ logits)
{
    extern __shared__ float sm[];
    float* s_wg = sm;
    float* s_x  = sm + Dz * Ez;

    const int tid = threadIdx.x;
    const int t0  = blockIdx.x * 128;
    const int b   = t0 >> 11;
    const int sbase = t0 & 2047;

    {
        const float4* wg4 = reinterpret_cast<const float4*>(Wg);
        float4* swg4 = reinterpret_cast<float4*>(s_wg);
#pragma unroll
        for (int q = 0; q < 32; q++) swg4[tid + 128 * q] = __ldg(wg4 + tid + 128 * q);
    }

    float acc[16];
#pragma unroll
    for (int e = 0; e < 16; e++) acc[e] = 0.f;

    const float* xb = x + (size_t)t0 * Dz;

    for (int k0 = 0; k0 < Dz; k0 += 32) {
        __syncthreads();
#pragma unroll
        for (int q = 0; q < 8; q++) {
            const int idx = tid + 128 * q;
            const int tt  = idx >> 3;
            const int c   = idx & 7;
            float4 v = __ldg(reinterpret_cast<const float4*>(xb + (size_t)tt * Dz + k0) + c);
            *reinterpret_cast<float4*>(&s_x[tt * 36 + 4 * c]) = v;
        }
        __syncthreads();

#pragma unroll
        for (int kq = 0; kq < 8; kq++) {
            const float4 xv = *reinterpret_cast<const float4*>(&s_x[tid * 36 + kq * 4]);
#pragma unroll
            for (int j = 0; j < 4; j++) {
                const float xs = (&xv.x)[j];
                const float4* wr = reinterpret_cast<const float4*>(&s_wg[(size_t)(k0 + kq * 4 + j) * Ez]);
                const float4 w0 = wr[0], w1 = wr[1], w2 = wr[2], w3 = wr[3];
                acc[0]  = fmaf(xs, w0.x, acc[0]);  acc[1]  = fmaf(xs, w0.y, acc[1]);
                acc[2]  = fmaf(xs, w0.z, acc[2]);  acc[3]  = fmaf(xs, w0.w, acc[3]);
                acc[4]  = fmaf(xs, w1.x, acc[4]);  acc[5]  = fmaf(xs, w1.y, acc[5]);
                acc[6]  = fmaf(xs, w1.z, acc[6]);  acc[7]  = fmaf(xs, w1.w, acc[7]);
                acc[8]  = fmaf(xs, w2.x, acc[8]);  acc[9]  = fmaf(xs, w2.y, acc[9]);
                acc[10] = fmaf(xs, w2.z, acc[10]); acc[11] = fmaf(xs, w2.w, acc[11]);
                acc[12] = fmaf(xs, w3.x, acc[12]); acc[13] = fmaf(xs, w3.y, acc[13]);
                acc[14] = fmaf(xs, w3.z, acc[14]); acc[15] = fmaf(xs, w3.w, acc[15]);
            }
        }
    }

#pragma unroll
    for (int e = 0; e < 16; e++)
        logits[((size_t)b * Ez + e) * Sz + sbase + tid] = acc[e];
}

// ---------------------------------------------------------------------------
// Kernel 2: top-4 + softmax stats (unchanged, exact)
// ---------------------------------------------------------------------------
__global__ void __launch_bounds__(256) topk_kernel(
    const float* __restrict__ logits,
    float* __restrict__ topv, int* __restrict__ topi)
{
    const int e = blockIdx.x;
    const int b = blockIdx.y;
    const int tid = threadIdx.x;
    const int wid = tid >> 5;
    const float* L = logits + ((size_t)b * Ez + e) * Sz;

    __shared__ float sl[Sz];
    __shared__ float redf[8];
    __shared__ int   redi[8];
    __shared__ float s_gmax, s_gsum;

    float m = -FLT_MAX;
#pragma unroll
    for (int q = 0; q < 8; q++) {
        const int s = tid + q * 256;
        const float v = __ldg(L + s);
        sl[s] = v;
        m = fmaxf(m, v);
    }
#pragma unroll
    for (int off = 16; off; off >>= 1) m = fmaxf(m, __shfl_xor_sync(0xffffffffu, m, off));
    if ((tid & 31) == 0) redf[wid] = m;
    __syncthreads();
    if (tid == 0) {
        float g = redf[0];
#pragma unroll
        for (int w = 1; w < 8; w++) g = fmaxf(g, redf[w]);
        s_gmax = g;
    }
    __syncthreads();
    const float gmax = s_gmax;

    float sum = 0.f;
#pragma unroll
    for (int q = 0; q < 8; q++) sum += expf(sl[tid + q * 256] - gmax);
#pragma unroll
    for (int off = 16; off; off >>= 1) sum += __shfl_xor_sync(0xffffffffu, sum, off);
    __syncthreads();
    if ((tid & 31) == 0) redf[wid] = sum;
    __syncthreads();
    if (tid == 0) {
        float g = 0.f;
#pragma unroll
        for (int w = 0; w < 8; w++) g += redf[w];
        s_gsum = g;
    }
    __syncthreads();
    const float gsum = s_gsum;

    for (int kk = 0; kk < 4; kk++) {
        float bv = -FLT_MAX;
        int   bi = 0x7fffffff;
#pragma unroll
        for (int q = 0; q < 8; q++) {
            const int s = tid + q * 256;
            const float v = sl[s];
            if (v > bv || (v == bv && s < bi)) { bv = v; bi = s; }
        }
#pragma unroll
        for (int off = 16; off; off >>= 1) {
            const float ov = __shfl_xor_sync(0xffffffffu, bv, off);
            const int   oi = __shfl_xor_sync(0xffffffffu, bi, off);
            if (ov > bv || (ov == bv && oi < bi)) { bv = ov; bi = oi; }
        }
        if ((tid & 31) == 0) { redf[wid] = bv; redi[wid] = bi; }
        __syncthreads();
        if (tid == 0) {
            float cv = redf[0]; int ci = redi[0];
#pragma unroll
            for (int w = 1; w < 8; w++) {
                if (redf[w] > cv || (redf[w] == cv && redi[w] < ci)) { cv = redf[w]; ci = redi[w]; }
            }
            const int base = (b * Ez + e) * Kz + kk;
            topi[base] = ci;
            topv[base] = expf(cv - gmax) / gsum;
            sl[ci] = -FLT_MAX;
        }
        __syncthreads();
    }
}

// ---------------------------------------------------------------------------
// Kernel 3: gather selected tokens (scaled) into [e][32][KD]
// ---------------------------------------------------------------------------
__global__ void __launch_bounds__(256) gather_kernel(
    const float* __restrict__ x, const int* __restrict__ topi,
    const float* __restrict__ topv, float* __restrict__ inp)
{
    const int k = blockIdx.x;
    const int e = blockIdx.y;
    const int b = blockIdx.z;
    const int base = (b * Ez + e) * Kz + k;
    const int idx = topi[base];
    const float val = topv[base];
    const float4* src = reinterpret_cast<const float4*>(x + ((size_t)b * Sz + idx) * Dz);
    float4* dst = reinterpret_cast<float4*>(inp + ((size_t)e * Bz + b) * KDz + (size_t)k * Dz);
    const int t = threadIdx.x;
    float4 v = src[t];
    v.x *= val; v.y *= val; v.z *= val; v.w *= val;
    dst[t] = v;
}

// ---------------------------------------------------------------------------
// Kernel 4: tf32 mma.sync grouped GEMM layer.
//   in  : [E][32][NI],  W : [E][NI][1024]
// CTA = (o-tile 128, expert), 128 threads (4 warps), warp owns 32x32 out tile.
// K chunks of 32 via 3-stage cp.async. smem pitches: A=36, W=136 (both
// conflict-free for m16n8k8 lane layouts).
// ---------------------------------------------------------------------------
#define A_PITCH 36
#define W_PITCH 136
#define STAGE_A_FLOATS (32 * A_PITCH)                 // 1152
#define STAGE_W_FLOATS (32 * W_PITCH)                 // 4352
#define STAGE_FLOATS   (STAGE_A_FLOATS + STAGE_W_FLOATS)   // 5504
#define SMEM_MLP_BYTES (3 * STAGE_FLOATS * 4)         // 66048
#define ST_PITCH 132

template <int NI, bool RELU, bool FINAL>
__global__ void __launch_bounds__(128) mlp_tc_kernel(
    const float* __restrict__ in, const float* __restrict__ W,
    const float* __restrict__ bias, float* __restrict__ out)
{
    constexpr int NC = NI / 32;        // k chunks
    extern __shared__ float sm[];
    const int tid = threadIdx.x;
    const int wid = tid >> 5;
    const int lane = tid & 31;
    const int e  = blockIdx.y;
    const int o0 = blockIdx.x * 128;

    const float* inE = in + (size_t)e * Bz * NI;
    const float* We  = W + (size_t)e * NI * Oz + o0;

    float acc[2][4][4];
#pragma unroll
    for (int mt = 0; mt < 2; mt++)
#pragma unroll
        for (int nt = 0; nt < 4; nt++)
#pragma unroll
            for (int r = 0; r < 4; r++) acc[mt][nt][r] = 0.f;

    // chunk loader: A 2 float4/thread + W 8 float4/thread
    auto load_chunk = [&](int ci, int stg) {
        const int k0 = ci * 32;
        float* sA = sm + stg * STAGE_FLOATS;
        float* sW = sA + STAGE_A_FLOATS;
        const uint32_t sAu = smem_u32(sA);
        const uint32_t sWu = smem_u32(sW);
#pragma unroll
        for (int q = 0; q < 2; q++) {
            const int idx = tid + q * 128;       // 0..255
            const int r = idx >> 3;              // batch row 0..31
            const int c = idx & 7;               // float4 col
            cp_async16(sAu + (r * A_PITCH + c * 4) * 4,
                       inE + (size_t)r * NI + k0 + c * 4);
        }
#pragma unroll
        for (int q = 0; q < 8; q++) {
            const int idx = tid + q * 128;       // 0..1023
            const int r = idx >> 5;              // k row 0..31
            const int c = idx & 31;              // float4 col 0..31
            cp_async16(sWu + (r * W_PITCH + c * 4) * 4,
                       We + (size_t)(k0 + r) * Oz + c * 4);
        }
    };

    load_chunk(0, 0); cp_commit();
    if (NC > 1) { load_chunk(1, 1); cp_commit(); }

    const int r4 = lane >> 2;
    const int c4 = lane & 3;

    for (int i = 0; i < NC; i++) {
        if (i < NC - 1) cp_wait<1>(); else cp_wait<0>();
        __syncthreads();

        const int stg = i % 3;
        const float* sA = sm + stg * STAGE_FLOATS;
        const float* sW = sA + STAGE_A_FLOATS;

#pragma unroll
        for (int k8 = 0; k8 < 4; k8++) {
            const int kb = k8 * 8;
            uint32_t a[2][4];
#pragma unroll
            for (int mt = 0; mt < 2; mt++) {
                const int mr = mt * 16 + r4;
                a[mt][0] = f2tf32(sA[(mr)     * A_PITCH + kb + c4]);
                a[mt][1] = f2tf32(sA[(mr + 8) * A_PITCH + kb + c4]);
                a[mt][2] = f2tf32(sA[(mr)     * A_PITCH + kb + c4 + 4]);
                a[mt][3] = f2tf32(sA[(mr + 8) * A_PITCH + kb + c4 + 4]);
            }
#pragma unroll
            for (int nt = 0; nt < 4; nt++) {
                const int n = wid * 32 + nt * 8 + r4;
                uint32_t b[2];
                b[0] = f2tf32(sW[(kb + c4)     * W_PITCH + n]);
                b[1] = f2tf32(sW[(kb + c4 + 4) * W_PITCH + n]);
                mma_tf32(acc[0][nt], a[0], b);
                mma_tf32(acc[1][nt], a[1], b);
            }
        }
        __syncthreads();

        if (i + 2 < NC) { load_chunk(i + 2, (i + 2) % 3); cp_commit(); }
    }

    // epilogue: stage fragments to smem, then coalesced bias(+relu) store
    float* st = sm;   // reuse stage 0 area (needs 32*132 = 4224 floats < 5504)
#pragma unroll
    for (int mt = 0; mt < 2; mt++)
#pragma unroll
        for (int nt = 0; nt < 4; nt++) {
            const int row = mt * 16 + r4;
            const int col = wid * 32 + nt * 8 + 2 * c4;
            st[row * ST_PITCH + col]           = acc[mt][nt][0];
            st[row * ST_PITCH + col + 1]       = acc[mt][nt][1];
            st[(row + 8) * ST_PITCH + col]     = acc[mt][nt][2];
            st[(row + 8) * ST_PITCH + col + 1] = acc[mt][nt][3];
        }
    __syncthreads();

#pragma unroll
    for (int q = 0; q < 8; q++) {
        const int idx = tid + q * 128;     // 0..1023 float4 slots
        const int b  = idx >> 5;           // batch 0..31
        const int c  = idx & 31;           // float4 col
        float4 v = *reinterpret_cast<const float4*>(&st[b * ST_PITCH + c * 4]);
        const float4 bv = __ldg(reinterpret_cast<const float4*>(bias + e * Oz + o0) + c);
        v.x += bv.x; v.y += bv.y; v.z += bv.z; v.w += bv.w;
        if (RELU) {
            v.x = fmaxf(v.x, 0.f); v.y = fmaxf(v.y, 0.f);
            v.z = fmaxf(v.z, 0.f); v.w = fmaxf(v.w, 0.f);
        }
        if (FINAL)
            reinterpret_cast<float4*>(out + ((size_t)b * Ez + e) * Oz + o0)[c] = v;
        else
            reinterpret_cast<float4*>(out + ((size_t)e * Bz + b) * Oz + o0)[c] = v;
    }
}

// ---------------------------------------------------------------------------
// Launch
// ---------------------------------------------------------------------------
extern "C" void kernel_launch(void* const* d_in, const int* in_sizes, int n_in,
                              void* d_out, int out_size)
{
    const float* x  = (const float*)d_in[0];
    const float* Wg = (const float*)d_in[1];
    // d_in[2] = bg : irrelevant (softmax over tokens is shift-invariant)
    const float* W1 = (const float*)d_in[3];
    const float* b1 = (const float*)d_in[4];
    const float* W2 = (const float*)d_in[5];
    const float* b2 = (const float*)d_in[6];
    const float* W3 = (const float*)d_in[7];
    const float* b3 = (const float*)d_in[8];
    float* out = (float*)d_out;

    float* logits; cudaGetSymbolAddress((void**)&logits, g_logits);
    float* topv;   cudaGetSymbolAddress((void**)&topv, g_topv);
    int*   topi;   cudaGetSymbolAddress((void**)&topi, g_topi);
    float* inp;    cudaGetSymbolAddress((void**)&inp, g_inp);
    float* h1;     cudaGetSymbolAddress((void**)&h1, g_h1);
    float* h2;     cudaGetSymbolAddress((void**)&h2, g_h2);

    const int gate_smem = (Dz * Ez + 128 * 36) * (int)sizeof(float);
    cudaFuncSetAttribute(gate_kernel, cudaFuncAttributeMaxDynamicSharedMemorySize, gate_smem);
    cudaFuncSetAttribute(mlp_tc_kernel<KDz, true,  false>, cudaFuncAttributeMaxDynamicSharedMemorySize, SMEM_MLP_BYTES);
    cudaFuncSetAttribute(mlp_tc_kernel<Oz,  true,  false>, cudaFuncAttributeMaxDynamicSharedMemorySize, SMEM_MLP_BYTES);
    cudaFuncSetAttribute(mlp_tc_kernel<Oz,  false, true >, cudaFuncAttributeMaxDynamicSharedMemorySize, SMEM_MLP_BYTES);

    gate_kernel<<<(Bz * Sz) / 128, 128, gate_smem>>>(x, Wg, logits);
    topk_kernel<<<dim3(Ez, Bz), 256>>>(logits, topv, topi);
    gather_kernel<<<dim3(Kz, Ez, Bz), 256>>>(x, topi, topv, inp);

    mlp_tc_kernel<KDz, true,  false><<<dim3(8, Ez), 128, SMEM_MLP_BYTES>>>(inp, W1, b1, h1);
    mlp_tc_kernel<Oz,  true,  false><<<dim3(8, Ez), 128, SMEM_MLP_BYTES>>>(h1, W2, b2, h2);
    mlp_tc_kernel<Oz,  false, true ><<<dim3(8, Ez), 128, SMEM_MLP_BYTES>>>(h2, W3, b3, out);
}